// round 8
// baseline (speedup 1.0000x reference)
#include <cuda_runtime.h>
#include <cuda_bf16.h>
#include <math.h>

#define BS_   64
#define NQ_   300
#define T_    1280            // 64 * 20 targets
#define ROWS_ (BS_ * NQ_)     // 19200
#define RPB_  16              // 1200 blocks, exact tiling
#define THREADS_ 320          // 1280 cols / 4 per thread

struct f2 { float x, y; };

__device__ __forceinline__ float frcp(float x) {
    float r;
    asm("rcp.approx.f32 %0, %1;" : "=f"(r) : "f"(x));
    return r;
}

// Packed f32x2 helpers with float-in/float-out interface: the .b64 staging
// registers live inside the asm block, so ptxas may allocate the scalar
// floats into aligned pairs and elide the MOVs entirely.
__device__ __forceinline__ f2 add2(f2 a, f2 b) {
    f2 r;
    asm("{.reg .b64 ra, rb, rc;\n\t"
        "mov.b64 ra, {%2, %3};\n\t"
        "mov.b64 rb, {%4, %5};\n\t"
        "add.rn.f32x2 rc, ra, rb;\n\t"
        "mov.b64 {%0, %1}, rc;}"
        : "=f"(r.x), "=f"(r.y)
        : "f"(a.x), "f"(a.y), "f"(b.x), "f"(b.y));
    return r;
}
__device__ __forceinline__ f2 mul2(f2 a, f2 b) {
    f2 r;
    asm("{.reg .b64 ra, rb, rc;\n\t"
        "mov.b64 ra, {%2, %3};\n\t"
        "mov.b64 rb, {%4, %5};\n\t"
        "mul.rn.f32x2 rc, ra, rb;\n\t"
        "mov.b64 {%0, %1}, rc;}"
        : "=f"(r.x), "=f"(r.y)
        : "f"(a.x), "f"(a.y), "f"(b.x), "f"(b.y));
    return r;
}
__device__ __forceinline__ f2 fma2(f2 a, f2 b, f2 c) {
    f2 r;
    asm("{.reg .b64 ra, rb, rc, rd;\n\t"
        "mov.b64 ra, {%2, %3};\n\t"
        "mov.b64 rb, {%4, %5};\n\t"
        "mov.b64 rc, {%6, %7};\n\t"
        "fma.rn.f32x2 rd, ra, rb, rc;\n\t"
        "mov.b64 {%0, %1}, rd;}"
        : "=f"(r.x), "=f"(r.y)
        : "f"(a.x), "f"(a.y), "f"(b.x), "f"(b.y), "f"(c.x), "f"(c.y));
    return r;
}

__global__ __launch_bounds__(THREADS_, 4)
void hungarian_cost_kernel(const float* __restrict__ logits,   // [ROWS_, 2]
                           const float* __restrict__ spans,    // [ROWS_, 2] (cx, w)
                           const float* __restrict__ tgt,      // [T_, 2]    (cx, w)
                           const float* __restrict__ refp,     // [ROWS_, 2]
                           float* __restrict__ out)            // [ROWS_, T_]
{
    // per-row constants: {2*cx, w, rc1, pad}
    __shared__ float4 s_row[RPB_];

    const int t    = threadIdx.x;          // owns columns 4t..4t+3
    const int row0 = blockIdx.x * RPB_;

    // ---- per-thread target constants (pair p covers cols 4t+2p, 4t+2p+1) ----
    const float4 ta = __ldg(reinterpret_cast<const float4*>(tgt) + 2 * t);
    const float4 tb = __ldg(reinterpret_cast<const float4*>(tgt) + 2 * t + 1);

    f2 NT2[2], NTW[2], TW[2];
    NT2[0] = { -2.0f * ta.x, -2.0f * ta.z };   // {-2*tcx}
    NT2[1] = { -2.0f * tb.x, -2.0f * tb.z };
    NTW[0] = { -ta.y, -ta.w };                 // {-tw}
    NTW[1] = { -tb.y, -tb.w };
    TW[0]  = {  ta.y,  ta.w };                 // {tw}
    TW[1]  = {  tb.y,  tb.w };
    const f2 NEG1 = { -1.0f, -1.0f };

    // ---- cooperative per-row constants (threads 0..RPB_-1) ----
    if (t < RPB_) {
        const int r = row0 + t;
        const float l0 = __ldg(logits + 2 * r);
        const float l1 = __ldg(logits + 2 * r + 1);
        const float m  = fmaxf(l0, l1);
        const float e0 = __expf(l0 - m);
        const float e1 = __expf(l1 - m);
        const float p0 = __fdividef(e0, e0 + e1);  // softmax prob class 0

        const float cx = __ldg(spans + 2 * r);
        const float w  = __ldg(spans + 2 * r + 1);
        const float hw = 0.5f * w;
        const float x1 = cx - hw;
        const float x2 = cx + hw;

        const float r0 = __ldg(refp + 2 * r);
        const float r1 = __ldg(refp + 2 * r + 1);
        const float d0 = fabsf(x1 - r0);
        const float d1 = fabsf(x2 - r1);
        const float cref = sqrtf(fmaf(d0, d0, d1 * d1));

        // rc1 = cost_reference - class_prob + 1  (+1 from -giou fold)
        s_row[t] = make_float4(2.0f * cx, w, cref - p0 + 1.0f, 0.0f);
    }
    __syncthreads();

    float4* op = reinterpret_cast<float4*>(out + (size_t)row0 * T_) + t;

#pragma unroll 4
    for (int rr = 0; rr < RPB_; ++rr) {
        const float4 rd = s_row[rr];
        const f2 c2p  = { rd.x, rd.x };   // {2cx, 2cx}
        const f2 wp   = { rd.y, rd.y };   // {w, w}
        const f2 rc1p = { rd.z, rd.z };   // {rc1, rc1}

        f2 vres[2];
#pragma unroll
        for (int p = 0; p < 2; ++p) {
            // Doubled coords: ri2 = s - M = 2*ri_true, U2 = 2s - I2, E2 = 2s - ri2.
            const f2 dc = add2(c2p, NT2[p]);     // 2cx - 2tcx
            const f2 dw = add2(wp,  NTW[p]);     // w - tw
            const f2 s  = add2(wp,  TW[p]);      // w + tw
            const f2 D  = add2(s, s);            // 2s

            // M = max(|2dcx|, |dw|): FMNMX with free abs modifiers
            const f2 M = { fmaxf(fabsf(dc.x), fabsf(dw.x)),
                           fmaxf(fabsf(dc.y), fabsf(dw.y)) };
            const f2 ri = fma2(M, NEG1, s);      // ri2 = s - M

            const f2 I = { fmaxf(ri.x, 0.0f), fmaxf(ri.y, 0.0f) };

            const f2 U  = fma2(I,  NEG1, D);     // U2 = 2s - I2
            const f2 nU = fma2(D,  NEG1, I);     // -U2
            const f2 E  = fma2(ri, NEG1, D);     // E2 = 2s - ri2

            const f2 pd = mul2(nU, E);           // -(U2*E2)
            const f2 rc = { frcp(pd.x), frcp(pd.y) };  // -1/(U2*E2)

            const f2 nA = mul2(I, E);            // I2*E2
            const f2 nB = fma2(U, U, nA);        // + U2^2

            // L1 span: 0.5*|2dcx| + |dw|, then + rc1
            const f2 bs = { fmaf(0.5f, fabsf(dc.x), fabsf(dw.x)),
                            fmaf(0.5f, fabsf(dc.y), fabsf(dw.y)) };
            const f2 bf = add2(bs, rc1p);

            // v = bf - (I2*E2 + U2^2)/(U2*E2)
            vres[p] = fma2(nB, rc, bf);
        }

        *op = make_float4(vres[0].x, vres[0].y, vres[1].x, vres[1].y);
        op += T_ / 4;
    }
}

extern "C" void kernel_launch(void* const* d_in, const int* in_sizes, int n_in,
                              void* d_out, int out_size) {
    const float* logits = (const float*)d_in[0];  // pred_logits [64,300,2]
    const float* spans  = (const float*)d_in[1];  // pred_spans  [64,300,2]
    const float* tgt    = (const float*)d_in[2];  // tgt_spans   [1280,2]
    const float* refp   = (const float*)d_in[3];  // ref_points  [64,300,2]
    float* out = (float*)d_out;                   // [64,300,1280] fp32

    hungarian_cost_kernel<<<ROWS_ / RPB_, THREADS_>>>(logits, spans, tgt, refp, out);
}

// round 10
// speedup vs baseline: 1.1023x; 1.1023x over previous
#include <cuda_runtime.h>
#include <cuda_bf16.h>
#include <math.h>

#define BS_   64
#define NQ_   300
#define T_    1280            // 64 * 20 targets
#define ROWS_ (BS_ * NQ_)     // 19200
#define RPB_  16              // 1200 blocks, exact tiling
#define THREADS_ 320          // 1280 cols / 4 per thread

typedef unsigned long long u64;

__device__ __forceinline__ float frcp(float x) {
    float r;
    asm("rcp.approx.f32 %0, %1;" : "=f"(r) : "f"(x));
    return r;
}
__device__ __forceinline__ u64 pk(float lo, float hi) {
    u64 r;
    asm("mov.b64 %0, {%1, %2};" : "=l"(r) : "f"(lo), "f"(hi));
    return r;
}
__device__ __forceinline__ void upk(u64 v, float& lo, float& hi) {
    asm("mov.b64 {%0, %1}, %2;" : "=f"(lo), "=f"(hi) : "l"(v));
}
__device__ __forceinline__ u64 add2(u64 a, u64 b) {
    u64 r;
    asm("add.rn.f32x2 %0, %1, %2;" : "=l"(r) : "l"(a), "l"(b));
    return r;
}
__device__ __forceinline__ u64 mul2(u64 a, u64 b) {
    u64 r;
    asm("mul.rn.f32x2 %0, %1, %2;" : "=l"(r) : "l"(a), "l"(b));
    return r;
}
__device__ __forceinline__ u64 fma2(u64 a, u64 b, u64 c) {
    u64 r;
    asm("fma.rn.f32x2 %0, %1, %2, %3;" : "=l"(r) : "l"(a), "l"(b), "l"(c));
    return r;
}

__global__ __launch_bounds__(THREADS_, 4)
void hungarian_cost_kernel(const float* __restrict__ logits,   // [ROWS_, 2]
                           const float* __restrict__ spans,    // [ROWS_, 2] (cx, w)
                           const float* __restrict__ tgt,      // [T_, 2]    (cx, w)
                           const float* __restrict__ refp,     // [ROWS_, 2]
                           float* __restrict__ out)            // [ROWS_, T_]
{
    // Row constants stored pre-duplicated for direct packed LDS:
    //  s_rowA[r] = { {2cx,2cx}, {w,w} }   (one LDS.128)
    //  s_rowB[r] = { rc1, rc1 }           (one LDS.64)
    __shared__ ulonglong2 s_rowA[RPB_];
    __shared__ u64        s_rowB[RPB_];

    const int t    = threadIdx.x;          // owns columns 4t..4t+3
    const int row0 = blockIdx.x * RPB_;

    // ---- per-thread target constants (pair p covers cols 4t+2p, 4t+2p+1) ----
    const float4 ta = __ldg(reinterpret_cast<const float4*>(tgt) + 2 * t);
    const float4 tb = __ldg(reinterpret_cast<const float4*>(tgt) + 2 * t + 1);

    u64 NT2[2], NTW[2], TW[2];
    NT2[0] = pk(-2.0f * ta.x, -2.0f * ta.z);   // {-2*tcx}
    NT2[1] = pk(-2.0f * tb.x, -2.0f * tb.z);
    NTW[0] = pk(-ta.y, -ta.w);                 // {-tw}
    NTW[1] = pk(-tb.y, -tb.w);
    TW[0]  = pk(ta.y, ta.w);                   // {tw}
    TW[1]  = pk(tb.y, tb.w);
    const u64 NEG1 = pk(-1.0f, -1.0f);

    // ---- cooperative per-row constants (threads 0..RPB_-1) ----
    if (t < RPB_) {
        const int r = row0 + t;
        const float l0 = __ldg(logits + 2 * r);
        const float l1 = __ldg(logits + 2 * r + 1);
        const float m  = fmaxf(l0, l1);
        const float e0 = __expf(l0 - m);
        const float e1 = __expf(l1 - m);
        const float p0 = __fdividef(e0, e0 + e1);  // softmax prob class 0

        const float cx = __ldg(spans + 2 * r);
        const float w  = __ldg(spans + 2 * r + 1);
        const float hw = 0.5f * w;
        const float x1 = cx - hw;
        const float x2 = cx + hw;

        const float r0 = __ldg(refp + 2 * r);
        const float r1 = __ldg(refp + 2 * r + 1);
        const float d0 = fabsf(x1 - r0);
        const float d1 = fabsf(x2 - r1);
        const float cref = sqrtf(fmaf(d0, d0, d1 * d1));
        const float rc1  = cref - p0 + 1.0f;   // ref - class_prob + 1 (giou fold)

        ulonglong2 a;
        a.x = pk(2.0f * cx, 2.0f * cx);
        a.y = pk(w, w);
        s_rowA[t] = a;
        s_rowB[t] = pk(rc1, rc1);
    }
    __syncthreads();

    ulonglong2* op = reinterpret_cast<ulonglong2*>(out + (size_t)row0 * T_) + t;

#pragma unroll 4
    for (int rr = 0; rr < RPB_; ++rr) {
        const ulonglong2 ra = s_rowA[rr];
        const u64 c2p  = ra.x;             // {2cx, 2cx}
        const u64 wp   = ra.y;             // {w, w}
        const u64 rc1p = s_rowB[rr];       // {rc1, rc1}

        u64 vres[2];
#pragma unroll
        for (int p = 0; p < 2; ++p) {
            // Doubled coords: ri2 = s - M, U2 = 2s - I2, E2 = 2s - ri2.
            const u64 dc2 = add2(c2p, NT2[p]);     // 2cx - 2tcx
            const u64 dw  = add2(wp,  NTW[p]);     // w - tw
            const u64 s   = add2(wp,  TW[p]);      // w + tw
            const u64 D   = add2(s, s);            // 2s

            float dca, dcb, dwa, dwb;
            upk(dc2, dca, dcb);
            upk(dw,  dwa, dwb);

            const float Ma = fmaxf(fabsf(dca), fabsf(dwa));
            const float Mb = fmaxf(fabsf(dcb), fabsf(dwb));
            const u64 Mp  = pk(Ma, Mb);
            const u64 rip = fma2(Mp, NEG1, s);     // ri2 = s - M

            float ria, rib;
            upk(rip, ria, rib);
            const float ia = fmaxf(ria, 0.0f);
            const float ib = fmaxf(rib, 0.0f);
            const u64 ip = pk(ia, ib);             // I2

            const u64 U  = fma2(ip,  NEG1, D);     // U2 = 2s - I2
            const u64 nU = fma2(D,   NEG1, ip);    // -U2
            const u64 E  = fma2(rip, NEG1, D);     // E2 = 2s - ri2

            const u64 pd = mul2(nU, E);            // {-den_a, -den_b}
            float pa, pb;
            upk(pd, pa, pb);
            const float dd = pa * pb;              // den_a * den_b  (>0)
            const float r  = frcp(dd);             // ONE rcp per pair
            const u64 pdsw = pk(pb, pa);           // swapped {-den_b, -den_a}
            const u64 rrp  = pk(r, r);

            const u64 numA = mul2(ip, E);          // I2*E2
            const u64 numB = fma2(U, U, numA);     // + U2^2

            // L1 span: 0.5*|2dcx| + |dw|; then + rc1
            const float basea = fmaf(0.5f, fabsf(dca), fabsf(dwa));
            const float baseb = fmaf(0.5f, fabsf(dcb), fabsf(dwb));
            const u64 bf = add2(pk(basea, baseb), rc1p);

            // num_a/den_a = num_a*(-den_b)*r  (r = 1/(den_a*den_b))
            // v = bf - num/den = bf + num*pdsw*r
            const u64 tmp = mul2(numB, pdsw);
            vres[p] = fma2(tmp, rrp, bf);
        }

        ulonglong2 o;
        o.x = vres[0];
        o.y = vres[1];
        *op = o;
        op += T_ / 4;
    }
}

extern "C" void kernel_launch(void* const* d_in, const int* in_sizes, int n_in,
                              void* d_out, int out_size) {
    const float* logits = (const float*)d_in[0];  // pred_logits [64,300,2]
    const float* spans  = (const float*)d_in[1];  // pred_spans  [64,300,2]
    const float* tgt    = (const float*)d_in[2];  // tgt_spans   [1280,2]
    const float* refp   = (const float*)d_in[3];  // ref_points  [64,300,2]
    float* out = (float*)d_out;                   // [64,300,1280] fp32

    hungarian_cost_kernel<<<ROWS_ / RPB_, THREADS_>>>(logits, spans, tgt, refp, out);
}